// round 9
// baseline (speedup 1.0000x reference)
#include <cuda_runtime.h>
#include <cuda_fp16.h>
#include <cstdint>

// Problem constants
#define B_   8
#define C_   128
#define H_   64
#define W_   64
#define COUT 128
#define KO   18
#define CK   1152          // C_*9, K reordered as k9*128 + c
#define KC   64            // K per chunk
#define NCHUNK (CK / KC)   // 18

// ---------------- f32x2 helpers (offconv) ----------------
__device__ __forceinline__ unsigned long long f32x2_pack(float lo, float hi) {
    unsigned long long r;
    asm("mov.b64 %0, {%1, %2};" : "=l"(r) : "f"(lo), "f"(hi));
    return r;
}
__device__ __forceinline__ void f32x2_unpack(float& lo, float& hi, unsigned long long v) {
    asm("mov.b64 {%0, %1}, %2;" : "=f"(lo), "=f"(hi) : "l"(v));
}
__device__ __forceinline__ void ffma2(unsigned long long& d, unsigned long long a,
                                      unsigned long long b) {
    asm("fma.rn.f32x2 %0, %1, %2, %0;" : "+l"(d) : "l"(a), "l"(b));
}

__device__ __forceinline__ uint32_t smem_to_u32(const void* p) {
    uint32_t a;
    asm("{ .reg .u64 t; cvta.to.shared.u64 t, %1; cvt.u32.u64 %0, t; }" : "=r"(a) : "l"(p));
    return a;
}

// cp.async 16B, L2-only (cg)
#define CP_ASYNC16(smem_addr, gptr) \
    asm volatile("cp.async.cg.shared.global [%0], [%1], 16;" \
                 :: "r"(smem_addr), "l"(gptr) : "memory")
#define CP_COMMIT()  asm volatile("cp.async.commit_group;" ::: "memory")
#define CP_WAIT0()   asm volatile("cp.async.wait_group 0;" ::: "memory")

// ldmatrix x4 (non-transposed)
#define LDSM4(r0, r1, r2, r3, addr) \
    asm volatile("ldmatrix.sync.aligned.m8n8.x4.shared.b16 {%0,%1,%2,%3}, [%4];" \
                 : "=r"(r0), "=r"(r1), "=r"(r2), "=r"(r3) : "r"(addr))

// fp16 mma with fp32 accumulate
#define MMA16816(c, a0, a1, a2, a3, b0, b1) \
    asm volatile("mma.sync.aligned.m16n8k16.row.col.f32.f16.f16.f32 " \
                 "{%0,%1,%2,%3},{%4,%5,%6,%7},{%8,%9},{%0,%1,%2,%3};" \
                 : "+f"((c)[0]), "+f"((c)[1]), "+f"((c)[2]), "+f"((c)[3]) \
                 : "r"(a0), "r"(a1), "r"(a2), "r"(a3), "r"(b0), "r"(b1))

// ---------------- device scratch ----------------
__device__ float g_off[B_ * KO * H_ * W_];
__device__ __align__(16) __half g_wh[COUT * CK];   // fp16 weights, K = k9*128 + c

// ---------------- kernel 0: fp16 weights, k9-major reorder ----------------
__global__ void k_prep_w(const float* __restrict__ w_def) {
    int i = blockIdx.x * blockDim.x + threadIdx.x;   // over COUT*CK (output layout)
    if (i < COUT * CK) {
        int cout = i / CK;
        int rem  = i - cout * CK;
        int k9   = rem >> 7;           // rem / 128
        int c    = rem & 127;
        g_wh[i] = __float2half(w_def[(cout * C_ + c) * 9 + k9]);
    }
}

// ---------------- kernel 1: offsets conv ----------------
#define OCC 8
__global__ void k_offconv(const float* __restrict__ x,
                          const float* __restrict__ w_off,
                          const float* __restrict__ b_off) {
    __shared__ float  xs[OCC][3][66];
    __shared__ float2 wf2[OCC][9][20];

    int b  = blockIdx.x >> 6;
    int ho = blockIdx.x & 63;
    int tid = threadIdx.x;
    int g   = tid >> 5;
    int wo  = tid & 31;

    unsigned long long accp[5];
    #pragma unroll
    for (int j = 0; j < 5; j++) accp[j] = 0ull;

    const float* xb = x + (size_t)b * C_ * H_ * W_;

    for (int c0 = 0; c0 < C_; c0 += OCC) {
        __syncthreads();
        for (int it = tid; it < OCC * 3 * 66; it += 128) {
            int cc  = it / 198;
            int rem = it - cc * 198;
            int r   = rem / 66;
            int col = rem - r * 66;
            int hy  = ho - 1 + r;
            int wx  = col - 1;
            float v = 0.f;
            if ((unsigned)hy < (unsigned)H_ && (unsigned)wx < (unsigned)W_)
                v = xb[(c0 + cc) * (H_ * W_) + hy * W_ + wx];
            xs[cc][r][col] = v;
        }
        for (int it = tid; it < OCC * 9 * 20; it += 128) {
            int cc  = it / 180;
            int rem = it - cc * 180;
            int kk  = rem / 20;
            int ko  = rem - kk * 20;
            float v = 0.f;
            if (ko < KO) v = w_off[((ko * C_) + (c0 + cc)) * 9 + kk];
            wf2[cc][kk][ko] = make_float2(v, v);
        }
        __syncthreads();

        #pragma unroll
        for (int cc = 0; cc < OCC; cc++) {
            #pragma unroll
            for (int r = 0; r < 3; r++) {
                unsigned long long xp0 = f32x2_pack(xs[cc][r][wo],     xs[cc][r][wo + 32]);
                unsigned long long xp1 = f32x2_pack(xs[cc][r][wo + 1], xs[cc][r][wo + 33]);
                unsigned long long xp2 = f32x2_pack(xs[cc][r][wo + 2], xs[cc][r][wo + 34]);
                #pragma unroll
                for (int kx = 0; kx < 3; kx++) {
                    unsigned long long xp = (kx == 0) ? xp0 : ((kx == 1) ? xp1 : xp2);
                    const unsigned long long* wrow =
                        (const unsigned long long*)&wf2[cc][r * 3 + kx][g * 5];
                    #pragma unroll
                    for (int j = 0; j < 5; j++) ffma2(accp[j], xp, wrow[j]);
                }
            }
        }
    }
    #pragma unroll
    for (int j = 0; j < 5; j++) {
        int ko = g * 5 + j;
        if (ko < KO) {
            float a0, a1;
            f32x2_unpack(a0, a1, accp[j]);
            float bb = b_off[ko];
            int base = ((b * KO + ko) * H_ + ho) * W_;
            g_off[base + wo]      = a0 + bb;
            g_off[base + wo + 32] = a1 + bb;
        }
    }
}

// ---------------- kernel 2: deformable conv, fp16 mma.sync, pipelined ----------------
// grid = B_*H_, blockDim = 256 (8 warps). Double-buffered A/B, one sync per chunk.
// Iteration order: prefetch(chunk+1) -> MMA(chunk) so LSU and tensor overlap via warp skew.
// SMEM layout (byte offsets), PITCH=144 (conflict-free ldmatrix):
#define PITCH 144
#define SA0   0                          // A buf0: 128 rows x 64 fp16
#define SA1   (SA0 + 128 * PITCH)        // 18432
#define SB0   (SA1 + 128 * PITCH)        // 36864: B buf0, 64 rows
#define SB1   (SB0 + 64 * PITCH)         // 46080
#define STAPW (SB1 + 64 * PITCH)         // 55296: 576 float4
#define STAPI (STAPW + 576 * 16)         // 64512: 576 int4
#define SBYTES (STAPI + 576 * 16)        // 73728

__global__ void __launch_bounds__(256, 3)
k_deform(const float* __restrict__ x, float* __restrict__ out) {
    extern __shared__ __align__(16) char smc[];
    uint32_t sb = smem_to_u32(smc);
    float4* tapW4 = (float4*)(smc + STAPW);
    int4*   tapI4 = (int4*)(smc + STAPI);

    int b   = blockIdx.x >> 6;
    int ho  = blockIdx.x & 63;
    int tid = threadIdx.x;
    int wid = tid >> 5;
    int lane = tid & 31;

    // ---- precompute bilinear taps for this row ----
    const float* goff = g_off + (size_t)(b * KO) * (H_ * W_) + ho * W_;
    for (int it = tid; it < 576; it += 256) {
        int k  = it >> 6;
        int wo = it & 63;
        float dy = goff[(2 * k)     * (H_ * W_) + wo];
        float dx = goff[(2 * k + 1) * (H_ * W_) + wo];
        float py = (float)(ho - 1 + (k / 3)) + dy;
        float px = (float)(wo - 1 + (k % 3)) + dx;
        float y0f = floorf(py), x0f = floorf(px);
        float wy = py - y0f,    wx = px - x0f;
        int y0 = (int)y0f, x0 = (int)x0f;
        int y1 = y0 + 1,   x1 = x0 + 1;
        float vy0 = (y0 >= 0 && y0 < H_) ? 1.f : 0.f;
        float vy1 = (y1 >= 0 && y1 < H_) ? 1.f : 0.f;
        float vx0 = (x0 >= 0 && x0 < W_) ? 1.f : 0.f;
        float vx1 = (x1 >= 0 && x1 < W_) ? 1.f : 0.f;
        int cy0 = min(max(y0, 0), H_ - 1), cy1 = min(max(y1, 0), H_ - 1);
        int cx0 = min(max(x0, 0), W_ - 1), cx1 = min(max(x1, 0), W_ - 1);
        tapI4[it] = make_int4(cy0 * W_ + cx0, cy0 * W_ + cx1,
                              cy1 * W_ + cx0, cy1 * W_ + cx1);
        tapW4[it] = make_float4((1.f - wy) * (1.f - wx) * vy0 * vx0,
                                (1.f - wy) * wx         * vy0 * vx1,
                                wy * (1.f - wx)         * vy1 * vx0,
                                wy * wx                 * vy1 * vx1);
    }
    __syncthreads();   // taps visible before first gather

    float c[8][4];
    #pragma unroll
    for (int i = 0; i < 8; i++)
        #pragma unroll
        for (int j = 0; j < 4; j++) c[i][j] = 0.f;

    const float* xb = x + (size_t)b * C_ * H_ * W_;
    const int n   = tid & 63;       // pixel this thread gathers
    const int t4  = tid >> 6;       // 0..3 -> 16-channel block

    // ldmatrix lane address components
    const int g8  = lane >> 3;
    const int lr  = lane & 7;
    const int m0  = wid * 16;
    const uint32_t a_row  = (uint32_t)(m0 + lr + (g8 & 1) * 8);
    const uint32_t a_koff = (uint32_t)((g8 >> 1) * 8);
    const uint32_t b_row  = (uint32_t)(lr + (g8 >> 1) * 8);
    const uint32_t b_koff = (uint32_t)((g8 & 1) * 8);

    const int a_m   = tid >> 1;          // A staging: row per thread pair
    const int a_c16 = (tid & 1) * 4;     // 64B half per thread

    // ---- stage helpers (inlined twice: prologue + loop) ----
    // A stage: 4 x cp.async 16B per thread
    // B stage: 16-channel gather + fp16 pack, one tap per chunk

    // prologue: fill buffer 0 with chunk 0
    {
        const char* src = (const char*)g_wh + (size_t)a_m * (CK * 2) + a_c16 * 16;
        uint32_t dst = sb + SA0 + a_m * PITCH + a_c16 * 16;
        CP_ASYNC16(dst,      src);
        CP_ASYNC16(dst + 16, src + 16);
        CP_ASYNC16(dst + 32, src + 32);
        CP_ASYNC16(dst + 48, src + 48);
        CP_COMMIT();

        int4   ti = tapI4[n];            // k9 = 0
        float4 tw = tapW4[n];
        const float* xc = xb + (size_t)(t4 * 16) * (H_ * W_);
        float v[16];
        #pragma unroll
        for (int jj = 0; jj < 16; jj++) {
            const float* xp = xc + (size_t)jj * (H_ * W_);
            float s;
            s = tw.x * __ldg(xp + ti.x);
            s = fmaf(tw.y, __ldg(xp + ti.y), s);
            s = fmaf(tw.z, __ldg(xp + ti.z), s);
            s = fmaf(tw.w, __ldg(xp + ti.w), s);
            v[jj] = s;
        }
        uint32_t* bw = (uint32_t*)(smc + SB0 + n * PITCH + t4 * 32);
        #pragma unroll
        for (int q = 0; q < 8; q++) {
            __half2 h2 = __floats2half2_rn(v[2 * q], v[2 * q + 1]);
            bw[q] = *(uint32_t*)&h2;
        }
        CP_WAIT0();
        __syncthreads();
    }

    for (int chunk = 0; chunk < NCHUNK; chunk++) {
        const int p = chunk & 1;

        // ---- prefetch chunk+1 into the other buffer (before MMA -> warp-skew overlap) ----
        if (chunk + 1 < NCHUNK) {
            const int nc  = chunk + 1;
            const int nk9 = nc >> 1;
            const int nc0 = (nc & 1) * 64;

            const char* src = (const char*)g_wh + (size_t)a_m * (CK * 2)
                              + nc * (KC * 2) + a_c16 * 16;
            uint32_t dst = sb + (p ? SA0 : SA1) + a_m * PITCH + a_c16 * 16;
            CP_ASYNC16(dst,      src);
            CP_ASYNC16(dst + 16, src + 16);
            CP_ASYNC16(dst + 32, src + 32);
            CP_ASYNC16(dst + 48, src + 48);
            CP_COMMIT();

            int tb = nk9 * 64 + n;
            int4   ti = tapI4[tb];
            float4 tw = tapW4[tb];
            const float* xc = xb + (size_t)(nc0 + t4 * 16) * (H_ * W_);
            float v[16];
            #pragma unroll
            for (int jj = 0; jj < 16; jj++) {
                const float* xp = xc + (size_t)jj * (H_ * W_);
                float s;
                s = tw.x * __ldg(xp + ti.x);
                s = fmaf(tw.y, __ldg(xp + ti.y), s);
                s = fmaf(tw.z, __ldg(xp + ti.z), s);
                s = fmaf(tw.w, __ldg(xp + ti.w), s);
                v[jj] = s;
            }
            uint32_t* bw = (uint32_t*)(smc + (p ? SB0 : SB1) + n * PITCH + t4 * 32);
            #pragma unroll
            for (int q = 0; q < 8; q++) {
                __half2 h2 = __floats2half2_rn(v[2 * q], v[2 * q + 1]);
                bw[q] = *(uint32_t*)&h2;
            }
        }

        // ---- MMA on current buffer p ----
        uint32_t Ab = sb + (p ? SA1 : SA0);
        uint32_t Bb = sb + (p ? SB1 : SB0);
        #pragma unroll
        for (int ks = 0; ks < 4; ks++) {
            uint32_t a0, a1, a2, a3;
            LDSM4(a0, a1, a2, a3, Ab + a_row * PITCH + (ks * 16 + a_koff) * 2);
            #pragma unroll
            for (int ng = 0; ng < 4; ng++) {
                uint32_t b0, b1, b2, b3;
                LDSM4(b0, b1, b2, b3, Bb + (ng * 16 + b_row) * PITCH + (ks * 16 + b_koff) * 2);
                MMA16816(c[ng * 2],     a0, a1, a2, a3, b0, b1);
                MMA16816(c[ng * 2 + 1], a0, a1, a2, a3, b2, b3);
            }
        }

        CP_WAIT0();        // A(chunk+1) landed
        __syncthreads();   // all MMA reads of p done; buffer p^1 fully written
    }

    // epilogue
    {
        int r0  = m0 + (lane >> 2);
        int col = 2 * (lane & 3);
        float* ob = out + (((size_t)(b * COUT)) * H_ + ho) * W_;
        #pragma unroll
        for (int t8 = 0; t8 < 8; t8++) {
            int nbase = t8 * 8 + col;
            float* p0 = ob + (size_t)r0 * (H_ * W_) + nbase;
            float* p1 = ob + (size_t)(r0 + 8) * (H_ * W_) + nbase;
            *(float2*)p0 = make_float2(c[t8][0], c[t8][1]);
            *(float2*)p1 = make_float2(c[t8][2], c[t8][3]);
        }
    }
}

// ---------------- launcher ----------------
extern "C" void kernel_launch(void* const* d_in, const int* in_sizes, int n_in,
                              void* d_out, int out_size) {
    const float* x     = (const float*)d_in[0];
    const float* w_off = (const float*)d_in[1];
    const float* b_off = (const float*)d_in[2];
    const float* w_def = (const float*)d_in[3];
    float* out = (float*)d_out;
    (void)in_sizes; (void)n_in; (void)out_size;

    k_prep_w<<<(COUT * CK + 255) / 256, 256>>>(w_def);
    k_offconv<<<B_ * H_, 128>>>(x, w_off, b_off);

    cudaFuncSetAttribute(k_deform, cudaFuncAttributeMaxDynamicSharedMemorySize, SBYTES);
    k_deform<<<B_ * H_, 256, SBYTES>>>(x, out);
}

// round 10
// speedup vs baseline: 1.1536x; 1.1536x over previous
#include <cuda_runtime.h>
#include <cuda_fp16.h>
#include <cstdint>

// Problem constants
#define B_   8
#define C_   128
#define H_   64
#define W_   64
#define COUT 128
#define KO   18
#define CK   1152          // C_*9, K reordered as k9*128 + c
#define KC   64            // K per chunk
#define NCHUNK (CK / KC)   // 18

// ---------------- f32x2 helpers (offconv) ----------------
__device__ __forceinline__ unsigned long long f32x2_pack(float lo, float hi) {
    unsigned long long r;
    asm("mov.b64 %0, {%1, %2};" : "=l"(r) : "f"(lo), "f"(hi));
    return r;
}
__device__ __forceinline__ void f32x2_unpack(float& lo, float& hi, unsigned long long v) {
    asm("mov.b64 {%0, %1}, %2;" : "=f"(lo), "=f"(hi) : "l"(v));
}
__device__ __forceinline__ void ffma2(unsigned long long& d, unsigned long long a,
                                      unsigned long long b) {
    asm("fma.rn.f32x2 %0, %1, %2, %0;" : "+l"(d) : "l"(a), "l"(b));
}

__device__ __forceinline__ uint32_t smem_to_u32(const void* p) {
    uint32_t a;
    asm("{ .reg .u64 t; cvta.to.shared.u64 t, %1; cvt.u32.u64 %0, t; }" : "=r"(a) : "l"(p));
    return a;
}

// ldmatrix x4 (non-transposed)
#define LDSM4(r0, r1, r2, r3, addr) \
    asm volatile("ldmatrix.sync.aligned.m8n8.x4.shared.b16 {%0,%1,%2,%3}, [%4];" \
                 : "=r"(r0), "=r"(r1), "=r"(r2), "=r"(r3) : "r"(addr))

// fp16 mma with fp32 accumulate
#define MMA16816(c, a0, a1, a2, a3, b0, b1) \
    asm volatile("mma.sync.aligned.m16n8k16.row.col.f32.f16.f16.f32 " \
                 "{%0,%1,%2,%3},{%4,%5,%6,%7},{%8,%9},{%0,%1,%2,%3};" \
                 : "+f"((c)[0]), "+f"((c)[1]), "+f"((c)[2]), "+f"((c)[3]) \
                 : "r"(a0), "r"(a1), "r"(a2), "r"(a3), "r"(b0), "r"(b1))

// ---------------- device scratch ----------------
__device__ float g_off[B_ * KO * H_ * W_];
__device__ __align__(16) __half g_wh[COUT * CK];            // fp16 weights, K = k9*128 + c
__device__ __align__(16) uint32_t g_xp[B_ * C_ * H_ * W_];  // half2(x[w], x[w+1]) pairs

// ---------------- kernel 0a: fp16 weights, k9-major reorder ----------------
__global__ void k_prep_w(const float* __restrict__ w_def) {
    int i = blockIdx.x * blockDim.x + threadIdx.x;
    if (i < COUT * CK) {
        int cout = i / CK;
        int rem  = i - cout * CK;
        int k9   = rem >> 7;
        int c    = rem & 127;
        g_wh[i] = __float2half(w_def[(cout * C_ + c) * 9 + k9]);
    }
}

// ---------------- kernel 0b: paired fp16 x ----------------
// thread handles 16 outputs (quarter of one (b,c,h) row)
__global__ void k_prep_x(const float* __restrict__ x) {
    int t = blockIdx.x * blockDim.x + threadIdx.x;     // over B_*C_*H_*4
    if (t >= B_ * C_ * H_ * 4) return;
    int qid = t & 3;
    int rid = t >> 2;                                  // (b,c,h)
    const float* row = x + (size_t)rid * W_;
    int base = qid * 16;
    float4 v0 = *(const float4*)(row + base);
    float4 v1 = *(const float4*)(row + base + 4);
    float4 v2 = *(const float4*)(row + base + 8);
    float4 v3 = *(const float4*)(row + base + 12);
    float nxt = (qid < 3) ? row[base + 16] : row[W_ - 1];
    float f[17] = {v0.x,v0.y,v0.z,v0.w, v1.x,v1.y,v1.z,v1.w,
                   v2.x,v2.y,v2.z,v2.w, v3.x,v3.y,v3.z,v3.w, nxt};
    uint32_t o[16];
    #pragma unroll
    for (int j = 0; j < 16; j++) {
        __half2 h2 = __floats2half2_rn(f[j], f[j + 1]);
        o[j] = *(uint32_t*)&h2;
    }
    uint4* dst = (uint4*)(g_xp + (size_t)rid * W_ + base);
    dst[0] = make_uint4(o[0], o[1], o[2], o[3]);
    dst[1] = make_uint4(o[4], o[5], o[6], o[7]);
    dst[2] = make_uint4(o[8], o[9], o[10], o[11]);
    dst[3] = make_uint4(o[12], o[13], o[14], o[15]);
}

// ---------------- kernel 1: offsets conv ----------------
#define OCC 8
__global__ void k_offconv(const float* __restrict__ x,
                          const float* __restrict__ w_off,
                          const float* __restrict__ b_off) {
    __shared__ float  xs[OCC][3][66];
    __shared__ float2 wf2[OCC][9][20];

    int b  = blockIdx.x >> 6;
    int ho = blockIdx.x & 63;
    int tid = threadIdx.x;
    int g   = tid >> 5;
    int wo  = tid & 31;

    unsigned long long accp[5];
    #pragma unroll
    for (int j = 0; j < 5; j++) accp[j] = 0ull;

    const float* xb = x + (size_t)b * C_ * H_ * W_;

    for (int c0 = 0; c0 < C_; c0 += OCC) {
        __syncthreads();
        for (int it = tid; it < OCC * 3 * 66; it += 128) {
            int cc  = it / 198;
            int rem = it - cc * 198;
            int r   = rem / 66;
            int col = rem - r * 66;
            int hy  = ho - 1 + r;
            int wx  = col - 1;
            float v = 0.f;
            if ((unsigned)hy < (unsigned)H_ && (unsigned)wx < (unsigned)W_)
                v = xb[(c0 + cc) * (H_ * W_) + hy * W_ + wx];
            xs[cc][r][col] = v;
        }
        for (int it = tid; it < OCC * 9 * 20; it += 128) {
            int cc  = it / 180;
            int rem = it - cc * 180;
            int kk  = rem / 20;
            int ko  = rem - kk * 20;
            float v = 0.f;
            if (ko < KO) v = w_off[((ko * C_) + (c0 + cc)) * 9 + kk];
            wf2[cc][kk][ko] = make_float2(v, v);
        }
        __syncthreads();

        #pragma unroll
        for (int cc = 0; cc < OCC; cc++) {
            #pragma unroll
            for (int r = 0; r < 3; r++) {
                unsigned long long xp0 = f32x2_pack(xs[cc][r][wo],     xs[cc][r][wo + 32]);
                unsigned long long xp1 = f32x2_pack(xs[cc][r][wo + 1], xs[cc][r][wo + 33]);
                unsigned long long xp2 = f32x2_pack(xs[cc][r][wo + 2], xs[cc][r][wo + 34]);
                #pragma unroll
                for (int kx = 0; kx < 3; kx++) {
                    unsigned long long xp = (kx == 0) ? xp0 : ((kx == 1) ? xp1 : xp2);
                    const unsigned long long* wrow =
                        (const unsigned long long*)&wf2[cc][r * 3 + kx][g * 5];
                    #pragma unroll
                    for (int j = 0; j < 5; j++) ffma2(accp[j], xp, wrow[j]);
                }
            }
        }
    }
    #pragma unroll
    for (int j = 0; j < 5; j++) {
        int ko = g * 5 + j;
        if (ko < KO) {
            float a0, a1;
            f32x2_unpack(a0, a1, accp[j]);
            float bb = b_off[ko];
            int base = ((b * KO + ko) * H_ + ho) * W_;
            g_off[base + wo]      = a0 + bb;
            g_off[base + wo + 32] = a1 + bb;
        }
    }
}

// ---------------- kernel 2: deformable conv, fp16 mma.sync, paired gather ----------------
// grid = B_*H_, blockDim = 256 (8 warps). R8 structure (2 syncs/chunk, single buffer).
// SMEM layout (byte offsets), PITCH=144 (conflict-free ldmatrix):
#define PITCH 144
#define SA    0                          // A: 128 rows x 64 fp16
#define SB    (SA + 128 * PITCH)         // 18432: B, 64 rows x 64 fp16
#define STAPW (SB + 64 * PITCH)          // 27648: 576 float4
#define STAPI (STAPW + 576 * 16)         // 36864: 576 int2
#define SBYTES (STAPI + 576 * 8)         // 41472

__global__ void __launch_bounds__(256)
k_deform(float* __restrict__ out) {
    extern __shared__ __align__(16) char smc[];
    uint32_t sb = smem_to_u32(smc);
    float4* tapW4 = (float4*)(smc + STAPW);
    int2*   tapI2 = (int2*)(smc + STAPI);

    int b   = blockIdx.x >> 6;
    int ho  = blockIdx.x & 63;
    int tid = threadIdx.x;
    int wid = tid >> 5;
    int lane = tid & 31;

    // ---- precompute bilinear taps: paired-column form with clamp folded into weights ----
    const float* goff = g_off + (size_t)(b * KO) * (H_ * W_) + ho * W_;
    for (int it = tid; it < 576; it += 256) {
        int k  = it >> 6;
        int wo = it & 63;
        float dy = goff[(2 * k)     * (H_ * W_) + wo];
        float dx = goff[(2 * k + 1) * (H_ * W_) + wo];
        float py = (float)(ho - 1 + (k / 3)) + dy;
        float px = (float)(wo - 1 + (k % 3)) + dx;
        float y0f = floorf(py), x0f = floorf(px);
        float wy = py - y0f,    wx = px - x0f;
        int y0 = (int)y0f, x0 = (int)x0f;
        int y1 = y0 + 1,   x1 = x0 + 1;
        float vy0 = (y0 >= 0 && y0 < H_) ? 1.f : 0.f;
        float vy1 = (y1 >= 0 && y1 < H_) ? 1.f : 0.f;
        float vx0 = (x0 >= 0 && x0 < W_) ? 1.f : 0.f;
        float vx1 = (x1 >= 0 && x1 < W_) ? 1.f : 0.f;
        int cy0 = min(max(y0, 0), H_ - 1), cy1 = min(max(y1, 0), H_ - 1);
        int cx0 = min(max(x0, 0), W_ - 1), cx1 = min(max(x1, 0), W_ - 1);
        // validity-folded raw weights per (row, col-tap)
        float w00 = (1.f - wy) * (1.f - wx) * vx0;   // row y0, col x0
        float w01 = (1.f - wy) * wx         * vx1;   // row y0, col x1
        float w10 = wy * (1.f - wx)         * vx0;   // row y1, col x0
        float w11 = wy * wx                 * vx1;   // row y1, col x1
        // remap clamped columns onto the aligned pair (bc, bc+1)
        int bc = min(max(x0, 0), W_ - 2);
        float a0 = (cx0 == bc)     ? 1.f : 0.f;
        float a1 = (cx0 == bc + 1) ? 1.f : 0.f;
        float b0 = (cx1 == bc)     ? 1.f : 0.f;
        float b1 = (cx1 == bc + 1) ? 1.f : 0.f;
        tapW4[it] = make_float4((w00 * a0 + w01 * b0) * vy0,   // wa row y0
                                (w00 * a1 + w01 * b1) * vy0,   // wb row y0
                                (w10 * a0 + w11 * b0) * vy1,   // wa row y1
                                (w10 * a1 + w11 * b1) * vy1);  // wb row y1
        tapI2[it] = make_int2(cy0 * W_ + bc, cy1 * W_ + bc);
    }
    __syncthreads();   // taps visible before first gather

    float c[8][4];
    #pragma unroll
    for (int i = 0; i < 8; i++)
        #pragma unroll
        for (int j = 0; j < 4; j++) c[i][j] = 0.f;

    const uint32_t* xpb = g_xp + (size_t)b * C_ * H_ * W_;
    const int n   = tid & 63;       // pixel this thread gathers
    const int t4  = tid >> 6;       // 0..3 -> 16-channel block

    // ldmatrix lane address components
    const int g8  = lane >> 3;
    const int lr  = lane & 7;
    const int m0  = wid * 16;
    const uint32_t a_row  = (uint32_t)(m0 + lr + (g8 & 1) * 8);
    const uint32_t a_koff = (uint32_t)((g8 >> 1) * 8);
    const uint32_t b_row  = (uint32_t)(lr + (g8 >> 1) * 8);
    const uint32_t b_koff = (uint32_t)((g8 & 1) * 8);

    const int a_m   = tid >> 1;          // A staging: row per thread pair
    const int a_c16 = (tid & 1) * 4;     // 64B half per thread

    for (int chunk = 0; chunk < NCHUNK; chunk++) {
        const int k9 = chunk >> 1;             // kernel position (0..8)
        const int c0 = (chunk & 1) * 64;       // channel half

        __syncthreads();   // prior MMA reads done before restage

        // ---- stage A (fp16 weights): 128 rows x 128B ----
        {
            const char* src = (const char*)g_wh + (size_t)a_m * (CK * 2)
                              + chunk * (KC * 2) + a_c16 * 16;
            char* dst = smc + SA + a_m * PITCH + a_c16 * 16;
            uint4 u0 = *(const uint4*)(src);
            uint4 u1 = *(const uint4*)(src + 16);
            uint4 u2 = *(const uint4*)(src + 32);
            uint4 u3 = *(const uint4*)(src + 48);
            *(uint4*)(dst)      = u0;
            *(uint4*)(dst + 16) = u1;
            *(uint4*)(dst + 32) = u2;
            *(uint4*)(dst + 48) = u3;
        }

        // ---- gather B: 16 channels, 2 paired LDG per value ----
        {
            int tb = k9 * 64 + n;
            int2   ti = tapI2[tb];
            float4 tw = tapW4[tb];
            const uint32_t* xc = xpb + (size_t)(c0 + t4 * 16) * (H_ * W_);
            float v[16];
            #pragma unroll
            for (int jj = 0; jj < 16; jj++) {
                const uint32_t* xp = xc + (size_t)jj * (H_ * W_);
                uint32_t u0 = __ldg(xp + ti.x);
                uint32_t u1 = __ldg(xp + ti.y);
                float2 f0 = __half22float2(*(__half2*)&u0);
                float2 f1 = __half22float2(*(__half2*)&u1);
                float s;
                s = tw.x * f0.x;
                s = fmaf(tw.y, f0.y, s);
                s = fmaf(tw.z, f1.x, s);
                s = fmaf(tw.w, f1.y, s);
                v[jj] = s;
            }
            uint32_t* bw = (uint32_t*)(smc + SB + n * PITCH + t4 * 32);
            #pragma unroll
            for (int q = 0; q < 8; q++) {
                __half2 h2 = __floats2half2_rn(v[2 * q], v[2 * q + 1]);
                bw[q] = *(uint32_t*)&h2;
            }
        }
        __syncthreads();   // A and B ready

        // ---- MMA: 4 k16-steps x 8 n8-tiles ----
        #pragma unroll
        for (int ks = 0; ks < 4; ks++) {
            uint32_t a0, a1, a2, a3;
            LDSM4(a0, a1, a2, a3, sb + SA + a_row * PITCH + (ks * 16 + a_koff) * 2);
            #pragma unroll
            for (int ng = 0; ng < 4; ng++) {
                uint32_t b0, b1, b2, b3;
                LDSM4(b0, b1, b2, b3, sb + SB + (ng * 16 + b_row) * PITCH + (ks * 16 + b_koff) * 2);
                MMA16816(c[ng * 2],     a0, a1, a2, a3, b0, b1);
                MMA16816(c[ng * 2 + 1], a0, a1, a2, a3, b2, b3);
            }
        }
    }

    // epilogue
    {
        int r0  = m0 + (lane >> 2);
        int col = 2 * (lane & 3);
        float* ob = out + (((size_t)(b * COUT)) * H_ + ho) * W_;
        #pragma unroll
        for (int t8 = 0; t8 < 8; t8++) {
            int nbase = t8 * 8 + col;
            float* p0 = ob + (size_t)r0 * (H_ * W_) + nbase;
            float* p1 = ob + (size_t)(r0 + 8) * (H_ * W_) + nbase;
            *(float2*)p0 = make_float2(c[t8][0], c[t8][1]);
            *(float2*)p1 = make_float2(c[t8][2], c[t8][3]);
        }
    }
}

// ---------------- launcher ----------------
extern "C" void kernel_launch(void* const* d_in, const int* in_sizes, int n_in,
                              void* d_out, int out_size) {
    const float* x     = (const float*)d_in[0];
    const float* w_off = (const float*)d_in[1];
    const float* b_off = (const float*)d_in[2];
    const float* w_def = (const float*)d_in[3];
    float* out = (float*)d_out;
    (void)in_sizes; (void)n_in; (void)out_size;

    k_prep_w<<<(COUT * CK + 255) / 256, 256>>>(w_def);
    k_prep_x<<<(B_ * C_ * H_ * 4 + 255) / 256, 256>>>(x);
    k_offconv<<<B_ * H_, 128>>>(x, w_off, b_off);

    cudaFuncSetAttribute(k_deform, cudaFuncAttributeMaxDynamicSharedMemorySize, SBYTES);
    k_deform<<<B_ * H_, 256, SBYTES>>>(out);
}

// round 11
// speedup vs baseline: 1.8986x; 1.6458x over previous
#include <cuda_runtime.h>
#include <cuda_fp16.h>
#include <cstdint>

// Problem constants
#define B_   8
#define C_   128
#define H_   64
#define W_   64
#define COUT 128
#define KO   18
#define CK   1152          // C_*9, K reordered as k9*128 + c
#define KC   64            // K per chunk
#define NCHUNK (CK / KC)   // 18
#define MOFF 32            // KO padded to 32 for MMA

__device__ __forceinline__ uint32_t smem_to_u32(const void* p) {
    uint32_t a;
    asm("{ .reg .u64 t; cvta.to.shared.u64 t, %1; cvt.u32.u64 %0, t; }" : "=r"(a) : "l"(p));
    return a;
}

// ldmatrix x4 (non-transposed)
#define LDSM4(r0, r1, r2, r3, addr) \
    asm volatile("ldmatrix.sync.aligned.m8n8.x4.shared.b16 {%0,%1,%2,%3}, [%4];" \
                 : "=r"(r0), "=r"(r1), "=r"(r2), "=r"(r3) : "r"(addr))

// fp16 mma with fp32 accumulate
#define MMA16816(c, a0, a1, a2, a3, b0, b1) \
    asm volatile("mma.sync.aligned.m16n8k16.row.col.f32.f16.f16.f32 " \
                 "{%0,%1,%2,%3},{%4,%5,%6,%7},{%8,%9},{%0,%1,%2,%3};" \
                 : "+f"((c)[0]), "+f"((c)[1]), "+f"((c)[2]), "+f"((c)[3]) \
                 : "r"(a0), "r"(a1), "r"(a2), "r"(a3), "r"(b0), "r"(b1))

// ---------------- device scratch ----------------
__device__ float g_off[B_ * KO * H_ * W_];
__device__ __align__(16) __half g_wh[COUT * CK];            // deform weights fp16, K = k9*128 + c
__device__ __align__(16) __half g_woh[MOFF * CK];           // offset-conv weights fp16, M padded
__device__ __align__(16) uint32_t g_xp[B_ * C_ * H_ * W_];  // half2(x[w], x[w+1]) pairs

// ---------------- kernel 0a: fp16 deform weights, k9-major reorder ----------------
__global__ void k_prep_w(const float* __restrict__ w_def) {
    int i = blockIdx.x * blockDim.x + threadIdx.x;
    if (i < COUT * CK) {
        int cout = i / CK;
        int rem  = i - cout * CK;
        int k9   = rem >> 7;
        int c    = rem & 127;
        g_wh[i] = __float2half(w_def[(cout * C_ + c) * 9 + k9]);
    }
}

// ---------------- kernel 0b: fp16 offset weights, k9-major, M padded to 32 ----------------
__global__ void k_prep_woff(const float* __restrict__ w_off) {
    int i = blockIdx.x * blockDim.x + threadIdx.x;
    if (i < MOFF * CK) {
        int m   = i / CK;
        int rem = i - m * CK;
        int k9  = rem >> 7;
        int c   = rem & 127;
        float v = (m < KO) ? w_off[(m * C_ + c) * 9 + k9] : 0.f;
        g_woh[i] = __float2half(v);
    }
}

// ---------------- kernel 0c: paired fp16 x ----------------
__global__ void k_prep_x(const float* __restrict__ x) {
    int t = blockIdx.x * blockDim.x + threadIdx.x;     // over B_*C_*H_*4
    if (t >= B_ * C_ * H_ * 4) return;
    int qid = t & 3;
    int rid = t >> 2;                                  // (b,c,h)
    const float* row = x + (size_t)rid * W_;
    int base = qid * 16;
    float4 v0 = *(const float4*)(row + base);
    float4 v1 = *(const float4*)(row + base + 4);
    float4 v2 = *(const float4*)(row + base + 8);
    float4 v3 = *(const float4*)(row + base + 12);
    float nxt = (qid < 3) ? row[base + 16] : row[W_ - 1];
    float f[17] = {v0.x,v0.y,v0.z,v0.w, v1.x,v1.y,v1.z,v1.w,
                   v2.x,v2.y,v2.z,v2.w, v3.x,v3.y,v3.z,v3.w, nxt};
    uint32_t o[16];
    #pragma unroll
    for (int j = 0; j < 16; j++) {
        __half2 h2 = __floats2half2_rn(f[j], f[j + 1]);
        o[j] = *(uint32_t*)&h2;
    }
    uint4* dst = (uint4*)(g_xp + (size_t)rid * W_ + base);
    dst[0] = make_uint4(o[0], o[1], o[2], o[3]);
    dst[1] = make_uint4(o[4], o[5], o[6], o[7]);
    dst[2] = make_uint4(o[8], o[9], o[10], o[11]);
    dst[3] = make_uint4(o[12], o[13], o[14], o[15]);
}

#define PITCH 144

// ---------------- kernel 1: offsets conv via fp16 mma.sync ----------------
// grid = B_*H_, blockDim = 256 (8 warps). off[32(pad)][64 px] = Woff[32][1152] * im2col.
// Chunk = one k9 x 64 channels; B staging is a coalesced shifted row read.
// Warp tile: wm = wid&1 -> m16 stripe; wn = wid>>1 -> n16 stripe.
__global__ void __launch_bounds__(256)
k_offmma(const float* __restrict__ x, const float* __restrict__ b_off) {
    __shared__ __align__(16) char smc[MOFF * PITCH + 64 * PITCH];
    char* smA = smc;
    char* smB = smc + MOFF * PITCH;
    uint32_t sbA = smem_to_u32(smA);
    uint32_t sbB = smem_to_u32(smB);

    int b   = blockIdx.x >> 6;
    int ho  = blockIdx.x & 63;
    int tid = threadIdx.x;
    int wid = tid >> 5;
    int lane = tid & 31;

    const int wm = wid & 1;        // m16 stripe
    const int wn = wid >> 1;       // n16 stripe (0..3)

    float c[2][4];
    #pragma unroll
    for (int i = 0; i < 2; i++)
        #pragma unroll
        for (int j = 0; j < 4; j++) c[i][j] = 0.f;

    const int n  = tid & 63;       // pixel this thread stages
    const int t4 = tid >> 6;       // 16-channel block

    // ldmatrix lane address components
    const int g8 = lane >> 3;
    const int lr = lane & 7;
    const uint32_t a_row  = (uint32_t)(wm * 16 + lr + (g8 & 1) * 8);
    const uint32_t a_koff = (uint32_t)((g8 >> 1) * 8);
    const uint32_t b_row  = (uint32_t)(wn * 16 + lr + (g8 >> 1) * 8);
    const uint32_t b_koff = (uint32_t)((g8 & 1) * 8);

    const int a_m   = tid >> 3;          // 0..31 rows
    const int a_c16 = tid & 7;           // 16B slot

    for (int chunk = 0; chunk < NCHUNK; chunk++) {
        const int k9 = chunk >> 1;
        const int c0 = (chunk & 1) * 64;
        const int ky = k9 / 3;
        const int kx = k9 - ky * 3;

        __syncthreads();   // prior MMA reads done

        // stage A: 32 rows x 128B
        {
            const char* src = (const char*)g_woh + (size_t)a_m * (CK * 2)
                              + chunk * (KC * 2) + a_c16 * 16;
            *(uint4*)(smA + a_m * PITCH + a_c16 * 16) = *(const uint4*)src;
        }

        // stage B: 16 channels, coalesced shifted row read, zero at borders
        {
            int row = ho + ky - 1;
            int col = n + kx - 1;
            bool ok = ((unsigned)row < (unsigned)H_) && ((unsigned)col < (unsigned)W_);
            const float* base = x + (((size_t)(b * C_ + c0 + t4 * 16) * H_ + row) * W_ + col);
            float v[16];
            #pragma unroll
            for (int jj = 0; jj < 16; jj++)
                v[jj] = ok ? __ldg(base + (size_t)jj * (H_ * W_)) : 0.f;
            uint32_t* bw = (uint32_t*)(smB + n * PITCH + t4 * 32);
            #pragma unroll
            for (int q = 0; q < 8; q++) {
                __half2 h2 = __floats2half2_rn(v[2 * q], v[2 * q + 1]);
                bw[q] = *(uint32_t*)&h2;
            }
        }
        __syncthreads();

        // MMA: m16 x n16 per warp, 4 k16-steps
        #pragma unroll
        for (int ks = 0; ks < 4; ks++) {
            uint32_t a0, a1, a2, a3;
            LDSM4(a0, a1, a2, a3, sbA + a_row * PITCH + (ks * 16 + a_koff) * 2);
            uint32_t b0, b1, b2, b3;
            LDSM4(b0, b1, b2, b3, sbB + b_row * PITCH + (ks * 16 + b_koff) * 2);
            MMA16816(c[0], a0, a1, a2, a3, b0, b1);
            MMA16816(c[1], a0, a1, a2, a3, b2, b3);
        }
    }

    // epilogue: add bias, store valid ko rows
    {
        int ko0 = wm * 16 + (lane >> 2);
        int ko1 = ko0 + 8;
        float bias0 = (ko0 < KO) ? __ldg(b_off + ko0) : 0.f;
        float bias1 = (ko1 < KO) ? __ldg(b_off + ko1) : 0.f;
        #pragma unroll
        for (int ng = 0; ng < 2; ng++) {
            int nb = wn * 16 + ng * 8 + 2 * (lane & 3);
            if (ko0 < KO) {
                float* p = g_off + (((size_t)(b * KO + ko0) * H_ + ho) * W_ + nb);
                *(float2*)p = make_float2(c[ng][0] + bias0, c[ng][1] + bias0);
            }
            if (ko1 < KO) {
                float* p = g_off + (((size_t)(b * KO + ko1) * H_ + ho) * W_ + nb);
                *(float2*)p = make_float2(c[ng][2] + bias1, c[ng][3] + bias1);
            }
        }
    }
}

// ---------------- kernel 2: deformable conv (unchanged from R10) ----------------
#define SA    0                          // A: 128 rows x 64 fp16
#define SB    (SA + 128 * PITCH)         // 18432: B, 64 rows x 64 fp16
#define STAPW (SB + 64 * PITCH)          // 27648: 576 float4
#define STAPI (STAPW + 576 * 16)         // 36864: 576 int2
#define SBYTES (STAPI + 576 * 8)         // 41472

__global__ void __launch_bounds__(256)
k_deform(float* __restrict__ out) {
    extern __shared__ __align__(16) char smc[];
    uint32_t sb = smem_to_u32(smc);
    float4* tapW4 = (float4*)(smc + STAPW);
    int2*   tapI2 = (int2*)(smc + STAPI);

    int b   = blockIdx.x >> 6;
    int ho  = blockIdx.x & 63;
    int tid = threadIdx.x;
    int wid = tid >> 5;
    int lane = tid & 31;

    // ---- precompute bilinear taps: paired-column form with clamp folded into weights ----
    const float* goff = g_off + (size_t)(b * KO) * (H_ * W_) + ho * W_;
    for (int it = tid; it < 576; it += 256) {
        int k  = it >> 6;
        int wo = it & 63;
        float dy = goff[(2 * k)     * (H_ * W_) + wo];
        float dx = goff[(2 * k + 1) * (H_ * W_) + wo];
        float py = (float)(ho - 1 + (k / 3)) + dy;
        float px = (float)(wo - 1 + (k % 3)) + dx;
        float y0f = floorf(py), x0f = floorf(px);
        float wy = py - y0f,    wx = px - x0f;
        int y0 = (int)y0f, x0 = (int)x0f;
        int y1 = y0 + 1,   x1 = x0 + 1;
        float vy0 = (y0 >= 0 && y0 < H_) ? 1.f : 0.f;
        float vy1 = (y1 >= 0 && y1 < H_) ? 1.f : 0.f;
        float vx0 = (x0 >= 0 && x0 < W_) ? 1.f : 0.f;
        float vx1 = (x1 >= 0 && x1 < W_) ? 1.f : 0.f;
        int cy0 = min(max(y0, 0), H_ - 1), cy1 = min(max(y1, 0), H_ - 1);
        int cx0 = min(max(x0, 0), W_ - 1), cx1 = min(max(x1, 0), W_ - 1);
        float w00 = (1.f - wy) * (1.f - wx) * vx0;
        float w01 = (1.f - wy) * wx         * vx1;
        float w10 = wy * (1.f - wx)         * vx0;
        float w11 = wy * wx                 * vx1;
        int bc = min(max(x0, 0), W_ - 2);
        float a0 = (cx0 == bc)     ? 1.f : 0.f;
        float a1 = (cx0 == bc + 1) ? 1.f : 0.f;
        float b0 = (cx1 == bc)     ? 1.f : 0.f;
        float b1 = (cx1 == bc + 1) ? 1.f : 0.f;
        tapW4[it] = make_float4((w00 * a0 + w01 * b0) * vy0,
                                (w00 * a1 + w01 * b1) * vy0,
                                (w10 * a0 + w11 * b0) * vy1,
                                (w10 * a1 + w11 * b1) * vy1);
        tapI2[it] = make_int2(cy0 * W_ + bc, cy1 * W_ + bc);
    }
    __syncthreads();

    float c[8][4];
    #pragma unroll
    for (int i = 0; i < 8; i++)
        #pragma unroll
        for (int j = 0; j < 4; j++) c[i][j] = 0.f;

    const uint32_t* xpb = g_xp + (size_t)b * C_ * H_ * W_;
    const int n   = tid & 63;
    const int t4  = tid >> 6;

    const int g8  = lane >> 3;
    const int lr  = lane & 7;
    const int m0  = wid * 16;
    const uint32_t a_row  = (uint32_t)(m0 + lr + (g8 & 1) * 8);
    const uint32_t a_koff = (uint32_t)((g8 >> 1) * 8);
    const uint32_t b_row  = (uint32_t)(lr + (g8 >> 1) * 8);
    const uint32_t b_koff = (uint32_t)((g8 & 1) * 8);

    const int a_m   = tid >> 1;
    const int a_c16 = (tid & 1) * 4;

    for (int chunk = 0; chunk < NCHUNK; chunk++) {
        const int k9 = chunk >> 1;
        const int c0 = (chunk & 1) * 64;

        __syncthreads();

        {
            const char* src = (const char*)g_wh + (size_t)a_m * (CK * 2)
                              + chunk * (KC * 2) + a_c16 * 16;
            char* dst = smc + SA + a_m * PITCH + a_c16 * 16;
            uint4 u0 = *(const uint4*)(src);
            uint4 u1 = *(const uint4*)(src + 16);
            uint4 u2 = *(const uint4*)(src + 32);
            uint4 u3 = *(const uint4*)(src + 48);
            *(uint4*)(dst)      = u0;
            *(uint4*)(dst + 16) = u1;
            *(uint4*)(dst + 32) = u2;
            *(uint4*)(dst + 48) = u3;
        }

        {
            int tb = k9 * 64 + n;
            int2   ti = tapI2[tb];
            float4 tw = tapW4[tb];
            const uint32_t* xc = xpb + (size_t)(c0 + t4 * 16) * (H_ * W_);
            float v[16];
            #pragma unroll
            for (int jj = 0; jj < 16; jj++) {
                const uint32_t* xp = xc + (size_t)jj * (H_ * W_);
                uint32_t u0 = __ldg(xp + ti.x);
                uint32_t u1 = __ldg(xp + ti.y);
                float2 f0 = __half22float2(*(__half2*)&u0);
                float2 f1 = __half22float2(*(__half2*)&u1);
                float s;
                s = tw.x * f0.x;
                s = fmaf(tw.y, f0.y, s);
                s = fmaf(tw.z, f1.x, s);
                s = fmaf(tw.w, f1.y, s);
                v[jj] = s;
            }
            uint32_t* bw = (uint32_t*)(smc + SB + n * PITCH + t4 * 32);
            #pragma unroll
            for (int q = 0; q < 8; q++) {
                __half2 h2 = __floats2half2_rn(v[2 * q], v[2 * q + 1]);
                bw[q] = *(uint32_t*)&h2;
            }
        }
        __syncthreads();

        #pragma unroll
        for (int ks = 0; ks < 4; ks++) {
            uint32_t a0, a1, a2, a3;
            LDSM4(a0, a1, a2, a3, sb + SA + a_row * PITCH + (ks * 16 + a_koff) * 2);
            #pragma unroll
            for (int ng = 0; ng < 4; ng++) {
                uint32_t b0, b1, b2, b3;
                LDSM4(b0, b1, b2, b3, sb + SB + (ng * 16 + b_row) * PITCH + (ks * 16 + b_koff) * 2);
                MMA16816(c[ng * 2],     a0, a1, a2, a3, b0, b1);
                MMA16816(c[ng * 2 + 1], a0, a1, a2, a3, b2, b3);
            }
        }
    }

    {
        int r0  = m0 + (lane >> 2);
        int col = 2 * (lane & 3);
        float* ob = out + (((size_t)(b * COUT)) * H_ + ho) * W_;
        #pragma unroll
        for (int t8 = 0; t8 < 8; t8++) {
            int nbase = t8 * 8 + col;
            float* p0 = ob + (size_t)r0 * (H_ * W_) + nbase;
            float* p1 = ob + (size_t)(r0 + 8) * (H_ * W_) + nbase;
            *(float2*)p0 = make_float2(c[t8][0], c[t8][1]);
            *(float2*)p1 = make_float2(c[t8][2], c[t8][3]);
        }
    }
}

// ---------------- launcher ----------------
extern "C" void kernel_launch(void* const* d_in, const int* in_sizes, int n_in,
                              void* d_out, int out_size) {
    const float* x     = (const float*)d_in[0];
    const float* w_off = (const float*)d_in[1];
    const float* b_off = (const float*)d_in[2];
    const float* w_def = (const float*)d_in[3];
    float* out = (float*)d_out;
    (void)in_sizes; (void)n_in; (void)out_size;

    k_prep_w<<<(COUT * CK + 255) / 256, 256>>>(w_def);
    k_prep_woff<<<(MOFF * CK + 255) / 256, 256>>>(w_off);
    k_prep_x<<<(B_ * C_ * H_ * 4 + 255) / 256, 256>>>(x);

    k_offmma<<<B_ * H_, 256>>>(x, b_off);

    cudaFuncSetAttribute(k_deform, cudaFuncAttributeMaxDynamicSharedMemorySize, SBYTES);
    k_deform<<<B_ * H_, 256, SBYTES>>>(out);
}